// round 6
// baseline (speedup 1.0000x reference)
#include <cuda_runtime.h>

#define B_  4
#define S_  2048
#define DM_ 512
#define H_  8
#define DK_ 64
#define SCALE_ 0.125f

typedef unsigned long long u64;

__device__ __forceinline__ void fma2(u64 &c, u64 a, u64 b) {
    asm("fma.rn.f32x2 %0, %1, %2, %0;" : "+l"(c) : "l"(a), "l"(b));
}
__device__ __forceinline__ u64 mul2(u64 a, u64 b) {
    u64 r; asm("mul.rn.f32x2 %0, %1, %2;" : "=l"(r) : "l"(a), "l"(b)); return r;
}
__device__ __forceinline__ u64 dup2(float a) {
    u64 r; asm("mov.b64 %0, {%1, %1};" : "=l"(r) : "f"(a)); return r;
}
__device__ __forceinline__ float2 unp(u64 v) {
    float2 f; asm("mov.b64 {%0, %1}, %2;" : "=f"(f.x), "=f"(f.y) : "l"(v)); return f;
}

// ---------------- scratch (device globals: allocation-free rule) -------------
__device__ float g_Q[B_*H_*S_*DK_];
__device__ float g_K[B_*H_*S_*DK_];
__device__ float g_V[B_*H_*S_*DK_];
__device__ float g_P[H_*S_*DK_];
__device__ float g_A[(size_t)B_*H_*S_*S_];
__device__ float g_ctx[B_*S_*DM_];

// ---------------------------------------------------------------------------
// GEMM body: C = X[.,512] @ W[512,512], 64x128 tile, double-buffered.
// Cols per thread: g*64 + tx*4 (g=0,1) -> LDS.128 b-operand, acc[i][g*2+k].
// ---------------------------------------------------------------------------
template<int SPLIT>
__device__ __forceinline__ void gemm_body(
    const float* __restrict__ X, const float* __restrict__ W,
    float* __restrict__ out, int m0, int n0,
    float2 (*As2)[64*18], float (*Bs)[16*128])
{
    const int tid = threadIdx.x;
    const int ty4 = (tid >> 4) * 4;
    const int tx  = tid & 15;
    const int ar = tid >> 2, ac = (tid & 3) * 4;
    const int br = tid >> 4, bc = (tid & 15) * 8;
    const float* Xp = &X[(size_t)(m0 + ar)*512 + ac];
    const float* Wp = &W[(size_t)br*512 + n0 + bc];

    u64 acc[4][4];
#pragma unroll
    for (int i = 0; i < 4; i++)
#pragma unroll
        for (int j = 0; j < 4; j++) acc[i][j] = 0ull;

    {
        float4 a4  = *(const float4*)Xp;
        float4 b40 = *(const float4*)&Wp[0];
        float4 b41 = *(const float4*)&Wp[4];
        As2[0][ar*18 + ac + 0] = make_float2(a4.x, a4.x);
        As2[0][ar*18 + ac + 1] = make_float2(a4.y, a4.y);
        As2[0][ar*18 + ac + 2] = make_float2(a4.z, a4.z);
        As2[0][ar*18 + ac + 3] = make_float2(a4.w, a4.w);
        *(float4*)&Bs[0][br*128 + bc]     = b40;
        *(float4*)&Bs[0][br*128 + bc + 4] = b41;
    }
    __syncthreads();

    for (int k0 = 0; k0 < 32; k0++) {
        const int cur = k0 & 1;
        float4 na, nb0, nb1;
        if (k0 < 31) {
            na  = *(const float4*)(Xp + (k0 + 1)*16);
            nb0 = *(const float4*)(Wp + (size_t)(k0 + 1)*16*512);
            nb1 = *(const float4*)(Wp + (size_t)(k0 + 1)*16*512 + 4);
        }
#pragma unroll
        for (int kk = 0; kk < 16; kk += 2) {
            ulonglong2 av2[4];
#pragma unroll
            for (int i = 0; i < 4; i++)
                av2[i] = *(const ulonglong2*)&As2[cur][(ty4 + i)*18 + kk];
            ulonglong2 b00 = *(const ulonglong2*)&Bs[cur][kk*128 + tx*4];
            ulonglong2 b01 = *(const ulonglong2*)&Bs[cur][kk*128 + 64 + tx*4];
            ulonglong2 b10 = *(const ulonglong2*)&Bs[cur][(kk+1)*128 + tx*4];
            ulonglong2 b11 = *(const ulonglong2*)&Bs[cur][(kk+1)*128 + 64 + tx*4];
#pragma unroll
            for (int i = 0; i < 4; i++) {
                fma2(acc[i][0], av2[i].x, b00.x);
                fma2(acc[i][1], av2[i].x, b00.y);
                fma2(acc[i][2], av2[i].x, b01.x);
                fma2(acc[i][3], av2[i].x, b01.y);
                fma2(acc[i][0], av2[i].y, b10.x);
                fma2(acc[i][1], av2[i].y, b10.y);
                fma2(acc[i][2], av2[i].y, b11.x);
                fma2(acc[i][3], av2[i].y, b11.y);
            }
        }
        if (k0 < 31) {
            const int nxt = cur ^ 1;
            As2[nxt][ar*18 + ac + 0] = make_float2(na.x, na.x);
            As2[nxt][ar*18 + ac + 1] = make_float2(na.y, na.y);
            As2[nxt][ar*18 + ac + 2] = make_float2(na.z, na.z);
            As2[nxt][ar*18 + ac + 3] = make_float2(na.w, na.w);
            *(float4*)&Bs[nxt][br*128 + bc]     = nb0;
            *(float4*)&Bs[nxt][br*128 + bc + 4] = nb1;
        }
        __syncthreads();
    }

#pragma unroll
    for (int i = 0; i < 4; i++) {
        const int mm = m0 + ty4 + i;
#pragma unroll
        for (int g = 0; g < 2; g++) {
            const int nn = n0 + g*64 + tx*4;
            float2 v0 = unp(acc[i][g*2]);
            float2 v1 = unp(acc[i][g*2 + 1]);
            float4 o4 = make_float4(v0.x, v0.y, v1.x, v1.y);
            if (SPLIT) {
                int bb = mm >> 11, ss = mm & 2047;
                int hh = nn >> 6,  dd = nn & 63;
                *(float4*)&out[((size_t)(bb*H_ + hh)*S_ + ss)*DK_ + dd] = o4;
            } else {
                *(float4*)&out[(size_t)mm*512 + nn] = o4;
            }
        }
    }
}

template<int SPLIT>
__global__ __launch_bounds__(256, 3) void gemm512_kernel(
    const float* __restrict__ X, const float* __restrict__ W,
    float* __restrict__ out)
{
    __shared__ float2 As2[2][64*18];
    __shared__ float  Bs[2][16*128];
    gemm_body<SPLIT>(X, W, out, blockIdx.x*64, blockIdx.y*128, As2, Bs);
}

// QKV fused: z selects which projection (better wave packing than 3 launches)
__global__ __launch_bounds__(256, 3) void qkv_kernel(
    const float* __restrict__ X,
    const float* __restrict__ Wq, const float* __restrict__ Wk,
    const float* __restrict__ Wv,
    float* __restrict__ oq, float* __restrict__ ok, float* __restrict__ ov)
{
    __shared__ float2 As2[2][64*18];
    __shared__ float  Bs[2][16*128];
    const float* W = (blockIdx.z == 0) ? Wq : (blockIdx.z == 1) ? Wk : Wv;
    float* out     = (blockIdx.z == 0) ? oq : (blockIdx.z == 1) ? ok : ov;
    gemm_body<1>(X, W, out, blockIdx.x*64, blockIdx.y*128, As2, Bs);
}

// ---------------------------------------------------------------------------
// A[bh,i,k] = sum_d (Q[bh,i,d]+v_bias[h,d]) * P[h,k,d]. 64x128 tile, K=64.
// Qd dup (float2, stride 66), Pt transposed [d][k] stride 132. 67.6KB smem.
// ---------------------------------------------------------------------------
__global__ __launch_bounds__(256, 3) void posA_kernel(
    const float* __restrict__ Qg0, const float* __restrict__ Pg0,
    const float* __restrict__ v_bias, float* __restrict__ Ag0)
{
    extern __shared__ float sm[];
    float2* Qd = (float2*)sm;          // [64*66] float2
    float*  Pt = sm + 2*64*66;         // [64*132]

    const int tid = threadIdx.x;
    const int ty4 = (tid >> 4) * 4;
    const int tx  = tid & 15;
    const int k0 = blockIdx.x * 128;
    const int i0 = blockIdx.y * 64;
    const int bh = blockIdx.z;
    const int h  = bh & 7;
    const float* Qg = Qg0 + (size_t)bh * S_ * DK_;
    const float* Pg = Pg0 + (size_t)h  * S_ * DK_;

    const int lr = tid >> 4;
    const int lc = (tid & 15) * 4;
#pragma unroll
    for (int rr = 0; rr < 4; rr++) {
        int r = lr + rr*16;
        float4 qv = *(const float4*)&Qg[(size_t)(i0 + r)*DK_ + lc];
        const float4 vb = *(const float4*)&v_bias[h*DK_ + lc];
        qv.x += vb.x; qv.y += vb.y; qv.z += vb.z; qv.w += vb.w;
        Qd[r*66 + lc + 0] = make_float2(qv.x, qv.x);
        Qd[r*66 + lc + 1] = make_float2(qv.y, qv.y);
        Qd[r*66 + lc + 2] = make_float2(qv.z, qv.z);
        Qd[r*66 + lc + 3] = make_float2(qv.w, qv.w);
    }
#pragma unroll
    for (int rr = 0; rr < 8; rr++) {      // P rows 0..127 transposed [d][k]
        int r = lr + rr*16;
        float4 pv = *(const float4*)&Pg[(size_t)(k0 + r)*DK_ + lc];
        Pt[(lc + 0)*132 + r] = pv.x;
        Pt[(lc + 1)*132 + r] = pv.y;
        Pt[(lc + 2)*132 + r] = pv.z;
        Pt[(lc + 3)*132 + r] = pv.w;
    }
    __syncthreads();

    u64 acc[4][4];
#pragma unroll
    for (int i = 0; i < 4; i++)
#pragma unroll
        for (int j = 0; j < 4; j++) acc[i][j] = 0ull;

#pragma unroll 2
    for (int d = 0; d < 64; d += 2) {
        ulonglong2 av2[4];
#pragma unroll
        for (int i = 0; i < 4; i++)
            av2[i] = *(const ulonglong2*)&Qd[(ty4 + i)*66 + d];
        ulonglong2 b00 = *(const ulonglong2*)&Pt[d*132 + tx*4];
        ulonglong2 b01 = *(const ulonglong2*)&Pt[d*132 + 64 + tx*4];
        ulonglong2 b10 = *(const ulonglong2*)&Pt[(d+1)*132 + tx*4];
        ulonglong2 b11 = *(const ulonglong2*)&Pt[(d+1)*132 + 64 + tx*4];
#pragma unroll
        for (int i = 0; i < 4; i++) {
            fma2(acc[i][0], av2[i].x, b00.x);
            fma2(acc[i][1], av2[i].x, b00.y);
            fma2(acc[i][2], av2[i].x, b01.x);
            fma2(acc[i][3], av2[i].x, b01.y);
            fma2(acc[i][0], av2[i].y, b10.x);
            fma2(acc[i][1], av2[i].y, b10.y);
            fma2(acc[i][2], av2[i].y, b11.x);
            fma2(acc[i][3], av2[i].y, b11.y);
        }
    }

    float* Ao = Ag0 + (size_t)bh * S_ * S_;
#pragma unroll
    for (int i = 0; i < 4; i++)
#pragma unroll
        for (int g = 0; g < 2; g++) {
            float2 v0 = unp(acc[i][g*2]);
            float2 v1 = unp(acc[i][g*2 + 1]);
            *(float4*)&Ao[(size_t)(i0 + ty4 + i)*S_ + k0 + g*64 + tx*4] =
                make_float4(v0.x, v0.y, v1.x, v1.y);
        }
}

// ---------------------------------------------------------------------------
// Fused flash attention. BM=64, BN=64, cols tx*4 per thread, 3 blocks/SM.
// smem: Qd (f2 stride 66) 33792 + U[64*68] 17408 + Vs[64*64] 16384 = 67584 B.
// ---------------------------------------------------------------------------
__global__ __launch_bounds__(256, 3) void flash_kernel(
    const float* __restrict__ Qg0, const float* __restrict__ Kg0,
    const float* __restrict__ Vg0, const float* __restrict__ Ag0,
    const float* __restrict__ u_bias, float* __restrict__ ctx)
{
    extern __shared__ float sm[];
    float2* Qd = (float2*)sm;          // [64*66] float2 dup(Q+u)
    float*  U  = sm + 2*64*66;         // [64*68]: Kt [d][col] / p [row][col]
    float*  Vs = U + 64*68;            // [64*64]

    const int tid = threadIdx.x;
    const int ty4 = (tid >> 4) * 4;
    const int tx  = tid & 15;
    const int i0 = blockIdx.x * 64;
    const int h = blockIdx.y, b = blockIdx.z;
    const int bh = b*H_ + h;
    const float* Qg = Qg0 + (size_t)bh * S_ * DK_;
    const float* Kg = Kg0 + (size_t)bh * S_ * DK_;
    const float* Vg = Vg0 + (size_t)bh * S_ * DK_;
    const float* Ag = Ag0 + (size_t)bh * S_ * S_;

    const int lr = tid >> 4;
    const int lc = (tid & 15) * 4;
#pragma unroll
    for (int rr = 0; rr < 4; rr++) {
        int r = lr + rr*16;
        float4 qv = *(const float4*)&Qg[(size_t)(i0 + r)*DK_ + lc];
        const float4 ub = *(const float4*)&u_bias[h*DK_ + lc];
        qv.x += ub.x; qv.y += ub.y; qv.z += ub.z; qv.w += ub.w;
        Qd[r*66 + lc + 0] = make_float2(qv.x, qv.x);
        Qd[r*66 + lc + 1] = make_float2(qv.y, qv.y);
        Qd[r*66 + lc + 2] = make_float2(qv.z, qv.z);
        Qd[r*66 + lc + 3] = make_float2(qv.w, qv.w);
    }

    float m[4], l[4];
    u64 O[4][2];
#pragma unroll
    for (int i = 0; i < 4; i++) {
        m[i] = -3.0e38f; l[i] = 0.f;
        O[i][0] = 0ull; O[i][1] = 0ull;
    }

    for (int jt = 0; jt < S_/64; jt++) {
        const int j0 = jt * 64;
        __syncthreads();
#pragma unroll
        for (int rr = 0; rr < 4; rr++) {   // K transposed into U, V row-major
            int r = lr + rr*16;
            float4 kv = *(const float4*)&Kg[(size_t)(j0 + r)*DK_ + lc];
            U[(lc + 0)*68 + r] = kv.x;
            U[(lc + 1)*68 + r] = kv.y;
            U[(lc + 2)*68 + r] = kv.z;
            U[(lc + 3)*68 + r] = kv.w;
            *(float4*)&Vs[r*64 + lc] =
                *(const float4*)&Vg[(size_t)(j0 + r)*DK_ + lc];
        }

        // prefetch shifted-A gather (independent of score GEMM)
        float ap[4][4];
#pragma unroll
        for (int i = 0; i < 4; i++) {
            const int gi = i0 + ty4 + i;
#pragma unroll
            for (int q = 0; q < 4; q++) {
                const int gj = j0 + tx*4 + q;
                float a;
                if (gj <= gi)          a = __ldg(&Ag[(size_t)gi*S_ + (S_-1 - gi + gj)]);
                else if (gj == gi + 1) a = 0.f;
                else                   a = __ldg(&Ag[(size_t)(gi+1)*S_ + (gj - gi - 2)]);
                ap[i][q] = a;
            }
        }
        __syncthreads();

        // ---- content scores: (Q+u) . K ----
        u64 acc[4][2];
#pragma unroll
        for (int i = 0; i < 4; i++) { acc[i][0] = 0ull; acc[i][1] = 0ull; }
#pragma unroll 4
        for (int d = 0; d < 64; d += 2) {
            ulonglong2 av2[4];
#pragma unroll
            for (int i = 0; i < 4; i++)
                av2[i] = *(const ulonglong2*)&Qd[(ty4 + i)*66 + d];
            ulonglong2 b0 = *(const ulonglong2*)&U[d*68 + tx*4];
            ulonglong2 b1 = *(const ulonglong2*)&U[(d+1)*68 + tx*4];
#pragma unroll
            for (int i = 0; i < 4; i++) {
                fma2(acc[i][0], av2[i].x, b0.x);
                fma2(acc[i][1], av2[i].x, b0.y);
                fma2(acc[i][0], av2[i].y, b1.x);
                fma2(acc[i][1], av2[i].y, b1.y);
            }
        }

        // ---- combine pos score, online softmax ----
        float ps[4][4];
#pragma unroll
        for (int i = 0; i < 4; i++) {
            float2 s0 = unp(acc[i][0]);
            float2 s1 = unp(acc[i][1]);
            ps[i][0] = (s0.x + ap[i][0]) * SCALE_;
            ps[i][1] = (s0.y + ap[i][1]) * SCALE_;
            ps[i][2] = (s1.x + ap[i][2]) * SCALE_;
            ps[i][3] = (s1.y + ap[i][3]) * SCALE_;
            float rmax = fmaxf(fmaxf(ps[i][0], ps[i][1]),
                               fmaxf(ps[i][2], ps[i][3]));
#pragma unroll
            for (int o = 8; o >= 1; o >>= 1)
                rmax = fmaxf(rmax, __shfl_xor_sync(0xffffffffu, rmax, o));
            const float mnew  = fmaxf(m[i], rmax);
            const float alpha = __expf(m[i] - mnew);
            float rsum = 0.f;
#pragma unroll
            for (int q = 0; q < 4; q++) {
                float e = __expf(ps[i][q] - mnew);
                ps[i][q] = e;
                rsum += e;
            }
#pragma unroll
            for (int o = 8; o >= 1; o >>= 1)
                rsum += __shfl_xor_sync(0xffffffffu, rsum, o);
            l[i] = l[i]*alpha + rsum;
            m[i] = mnew;
            const u64 al = dup2(alpha);
            O[i][0] = mul2(O[i][0], al);
            O[i][1] = mul2(O[i][1], al);
        }

        __syncthreads();   // Kt reads done before overwriting U with p
#pragma unroll
        for (int i = 0; i < 4; i++)
            *(float4*)&U[(ty4 + i)*68 + tx*4] =
                make_float4(ps[i][0], ps[i][1], ps[i][2], ps[i][3]);
        __syncthreads();

        // ---- O += p @ V ----
#pragma unroll 2
        for (int j = 0; j < 64; j += 4) {
            float4 pq[4];
#pragma unroll
            for (int i = 0; i < 4; i++)
                pq[i] = *(const float4*)&U[(ty4 + i)*68 + j];
            ulonglong2 vv0 = *(const ulonglong2*)&Vs[(j+0)*64 + tx*4];
            ulonglong2 vv1 = *(const ulonglong2*)&Vs[(j+1)*64 + tx*4];
            ulonglong2 vv2 = *(const ulonglong2*)&Vs[(j+2)*64 + tx*4];
            ulonglong2 vv3 = *(const ulonglong2*)&Vs[(j+3)*64 + tx*4];
#pragma unroll
            for (int i = 0; i < 4; i++) {
                u64 a;
                a = dup2(pq[i].x); fma2(O[i][0], a, vv0.x); fma2(O[i][1], a, vv0.y);
                a = dup2(pq[i].y); fma2(O[i][0], a, vv1.x); fma2(O[i][1], a, vv1.y);
                a = dup2(pq[i].z); fma2(O[i][0], a, vv2.x); fma2(O[i][1], a, vv2.y);
                a = dup2(pq[i].w); fma2(O[i][0], a, vv3.x); fma2(O[i][1], a, vv3.y);
            }
        }
    }

    // epilogue: normalize, write context as [B,S,H*DK]
#pragma unroll
    for (int i = 0; i < 4; i++) {
        const int gi = i0 + ty4 + i;
        const float inv = 1.0f / l[i];
        float2 o0 = unp(O[i][0]);
        float2 o1 = unp(O[i][1]);
        float4 o4 = make_float4(o0.x*inv, o0.y*inv, o1.x*inv, o1.y*inv);
        *(float4*)&ctx[((size_t)b*S_ + gi)*DM_ + h*DK_ + tx*4] = o4;
    }
}

// ---------------------------------------------------------------------------
extern "C" void kernel_launch(void* const* d_in, const int* in_sizes, int n_in,
                              void* d_out, int out_size)
{
    (void)in_sizes; (void)n_in; (void)out_size;
    const float* inputs  = (const float*)d_in[0];
    const float* pos_enc = (const float*)d_in[1];
    const float* W_q     = (const float*)d_in[2];
    const float* W_k     = (const float*)d_in[3];
    const float* W_v     = (const float*)d_in[4];
    const float* W_o     = (const float*)d_in[5];
    const float* W_pos   = (const float*)d_in[6];
    const float* u_b     = (const float*)d_in[7];
    const float* v_b     = (const float*)d_in[8];
    float* out = (float*)d_out;

    float *qp, *kp, *vp, *pp, *ap, *cp;
    cudaGetSymbolAddress((void**)&qp, g_Q);
    cudaGetSymbolAddress((void**)&kp, g_K);
    cudaGetSymbolAddress((void**)&vp, g_V);
    cudaGetSymbolAddress((void**)&pp, g_P);
    cudaGetSymbolAddress((void**)&ap, g_A);
    cudaGetSymbolAddress((void**)&cp, g_ctx);

    const int POSA_SMEM  = (2*64*66 + 64*132) * (int)sizeof(float);          // 67584
    const int FLASH_SMEM = (2*64*66 + 64*68 + 64*64) * (int)sizeof(float);   // 67584
    cudaFuncSetAttribute(posA_kernel,
                         cudaFuncAttributeMaxDynamicSharedMemorySize, POSA_SMEM);
    cudaFuncSetAttribute(flash_kernel,
                         cudaFuncAttributeMaxDynamicSharedMemorySize, FLASH_SMEM);
    cudaFuncSetAttribute(posA_kernel,
                         cudaFuncAttributePreferredSharedMemoryCarveout, 100);
    cudaFuncSetAttribute(flash_kernel,
                         cudaFuncAttributePreferredSharedMemoryCarveout, 100);

    const dim3 thr(256);
    // fused Q/K/V projections (head-split layout), one launch
    qkv_kernel<<<dim3(128, 4, 3), thr>>>(inputs, W_q, W_k, W_v, qp, kp, vp);
    // pos projection
    gemm512_kernel<1><<<dim3(32, 4), thr>>>(pos_enc, W_pos, pp);
    // pos matrix A = (Q+v) @ P^T per (b,h)
    posA_kernel<<<dim3(16, 32, 32), thr, POSA_SMEM>>>(qp, pp, v_b, ap);
    // fused attention -> g_ctx
    flash_kernel<<<dim3(32, 8, 4), thr, FLASH_SMEM>>>(qp, kp, vp, ap, u_b, cp);
    // output projection: ctx @ W_o -> out
    gemm512_kernel<0><<<dim3(128, 4), thr>>>(cp, W_o, out);
}

// round 10
// speedup vs baseline: 1.0309x; 1.0309x over previous
#include <cuda_runtime.h>

#define B_  4
#define S_  2048
#define DM_ 512
#define H_  8
#define DK_ 64
#define SCALE_ 0.125f

typedef unsigned long long u64;

__device__ __forceinline__ void fma2(u64 &c, u64 a, u64 b) {
    asm("fma.rn.f32x2 %0, %1, %2, %0;" : "+l"(c) : "l"(a), "l"(b));
}
__device__ __forceinline__ u64 mul2(u64 a, u64 b) {
    u64 r; asm("mul.rn.f32x2 %0, %1, %2;" : "=l"(r) : "l"(a), "l"(b)); return r;
}
__device__ __forceinline__ u64 dup2(float a) {
    u64 r; asm("mov.b64 %0, {%1, %1};" : "=l"(r) : "f"(a)); return r;
}
__device__ __forceinline__ float2 unp(u64 v) {
    float2 f; asm("mov.b64 {%0, %1}, %2;" : "=f"(f.x), "=f"(f.y) : "l"(v)); return f;
}

// ---------------- scratch (device globals: allocation-free rule) -------------
__device__ float g_Q[B_*H_*S_*DK_];
__device__ float g_K[B_*H_*S_*DK_];
__device__ float g_V[B_*H_*S_*DK_];
__device__ float g_P[H_*S_*DK_];
__device__ float g_A[(size_t)B_*H_*S_*S_];
__device__ float g_ctx[B_*S_*DM_];

// ---------------------------------------------------------------------------
// GEMM body: C = X[.,512] @ W[512,512], 64x128 tile, double-buffered, f32x2.
// ---------------------------------------------------------------------------
template<int SPLIT>
__device__ __forceinline__ void gemm_body(
    const float* __restrict__ X, const float* __restrict__ W,
    float* __restrict__ out, int m0, int n0,
    float2 (*As2)[64*18], float (*Bs)[16*128])
{
    const int tid = threadIdx.x;
    const int ty4 = (tid >> 4) * 4;
    const int tx  = tid & 15;
    const int ar = tid >> 2, ac = (tid & 3) * 4;
    const int br = tid >> 4, bc = (tid & 15) * 8;
    const float* Xp = &X[(size_t)(m0 + ar)*512 + ac];
    const float* Wp = &W[(size_t)br*512 + n0 + bc];

    u64 acc[4][4];
#pragma unroll
    for (int i = 0; i < 4; i++)
#pragma unroll
        for (int j = 0; j < 4; j++) acc[i][j] = 0ull;

    {
        float4 a4  = *(const float4*)Xp;
        float4 b40 = *(const float4*)&Wp[0];
        float4 b41 = *(const float4*)&Wp[4];
        As2[0][ar*18 + ac + 0] = make_float2(a4.x, a4.x);
        As2[0][ar*18 + ac + 1] = make_float2(a4.y, a4.y);
        As2[0][ar*18 + ac + 2] = make_float2(a4.z, a4.z);
        As2[0][ar*18 + ac + 3] = make_float2(a4.w, a4.w);
        *(float4*)&Bs[0][br*128 + bc]     = b40;
        *(float4*)&Bs[0][br*128 + bc + 4] = b41;
    }
    __syncthreads();

    for (int k0 = 0; k0 < 32; k0++) {
        const int cur = k0 & 1;
        float4 na, nb0, nb1;
        if (k0 < 31) {
            na  = *(const float4*)(Xp + (k0 + 1)*16);
            nb0 = *(const float4*)(Wp + (size_t)(k0 + 1)*16*512);
            nb1 = *(const float4*)(Wp + (size_t)(k0 + 1)*16*512 + 4);
        }
#pragma unroll
        for (int kk = 0; kk < 16; kk += 2) {
            ulonglong2 av2[4];
#pragma unroll
            for (int i = 0; i < 4; i++)
                av2[i] = *(const ulonglong2*)&As2[cur][(ty4 + i)*18 + kk];
            ulonglong2 b00 = *(const ulonglong2*)&Bs[cur][kk*128 + tx*4];
            ulonglong2 b01 = *(const ulonglong2*)&Bs[cur][kk*128 + 64 + tx*4];
            ulonglong2 b10 = *(const ulonglong2*)&Bs[cur][(kk+1)*128 + tx*4];
            ulonglong2 b11 = *(const ulonglong2*)&Bs[cur][(kk+1)*128 + 64 + tx*4];
#pragma unroll
            for (int i = 0; i < 4; i++) {
                fma2(acc[i][0], av2[i].x, b00.x);
                fma2(acc[i][1], av2[i].x, b00.y);
                fma2(acc[i][2], av2[i].x, b01.x);
                fma2(acc[i][3], av2[i].x, b01.y);
                fma2(acc[i][0], av2[i].y, b10.x);
                fma2(acc[i][1], av2[i].y, b10.y);
                fma2(acc[i][2], av2[i].y, b11.x);
                fma2(acc[i][3], av2[i].y, b11.y);
            }
        }
        if (k0 < 31) {
            const int nxt = cur ^ 1;
            As2[nxt][ar*18 + ac + 0] = make_float2(na.x, na.x);
            As2[nxt][ar*18 + ac + 1] = make_float2(na.y, na.y);
            As2[nxt][ar*18 + ac + 2] = make_float2(na.z, na.z);
            As2[nxt][ar*18 + ac + 3] = make_float2(na.w, na.w);
            *(float4*)&Bs[nxt][br*128 + bc]     = nb0;
            *(float4*)&Bs[nxt][br*128 + bc + 4] = nb1;
        }
        __syncthreads();
    }

#pragma unroll
    for (int i = 0; i < 4; i++) {
        const int mm = m0 + ty4 + i;
#pragma unroll
        for (int g = 0; g < 2; g++) {
            const int nn = n0 + g*64 + tx*4;
            float2 v0 = unp(acc[i][g*2]);
            float2 v1 = unp(acc[i][g*2 + 1]);
            float4 o4 = make_float4(v0.x, v0.y, v1.x, v1.y);
            if (SPLIT) {
                int bb = mm >> 11, ss = mm & 2047;
                int hh = nn >> 6,  dd = nn & 63;
                *(float4*)&out[((size_t)(bb*H_ + hh)*S_ + ss)*DK_ + dd] = o4;
            } else {
                *(float4*)&out[(size_t)mm*512 + nn] = o4;
            }
        }
    }
}

template<int SPLIT>
__global__ __launch_bounds__(256, 3) void gemm512_kernel(
    const float* __restrict__ X, const float* __restrict__ W,
    float* __restrict__ out)
{
    __shared__ float2 As2[2][64*18];
    __shared__ float  Bs[2][16*128];
    gemm_body<SPLIT>(X, W, out, blockIdx.x*64, blockIdx.y*128, As2, Bs);
}

__global__ __launch_bounds__(256, 3) void qkv_kernel(
    const float* __restrict__ X,
    const float* __restrict__ Wq, const float* __restrict__ Wk,
    const float* __restrict__ Wv,
    float* __restrict__ oq, float* __restrict__ ok, float* __restrict__ ov)
{
    __shared__ float2 As2[2][64*18];
    __shared__ float  Bs[2][16*128];
    const float* W = (blockIdx.z == 0) ? Wq : (blockIdx.z == 1) ? Wk : Wv;
    float* out     = (blockIdx.z == 0) ? oq : (blockIdx.z == 1) ? ok : ov;
    gemm_body<1>(X, W, out, blockIdx.x*64, blockIdx.y*128, As2, Bs);
}

// ---------------------------------------------------------------------------
// A[bh,i,k] = sum_d (Q[bh,i,d]+v_bias[h,d]) * P[h,k,d]. 64x128 tile, K=64.
// Qd dup (float2, stride 66), Pt transposed [d][k] stride 132. 67.6KB smem.
// ---------------------------------------------------------------------------
__global__ __launch_bounds__(256, 3) void posA_kernel(
    const float* __restrict__ Qg0, const float* __restrict__ Pg0,
    const float* __restrict__ v_bias, float* __restrict__ Ag0)
{
    extern __shared__ float sm[];
    float2* Qd = (float2*)sm;          // [64*66] float2
    float*  Pt = sm + 2*64*66;         // [64*132]

    const int tid = threadIdx.x;
    const int ty4 = (tid >> 4) * 4;
    const int tx  = tid & 15;
    const int k0 = blockIdx.x * 128;
    const int i0 = blockIdx.y * 64;
    const int bh = blockIdx.z;
    const int h  = bh & 7;
    const float* Qg = Qg0 + (size_t)bh * S_ * DK_;
    const float* Pg = Pg0 + (size_t)h  * S_ * DK_;

    const int lr = tid >> 4;
    const int lc = (tid & 15) * 4;
#pragma unroll
    for (int rr = 0; rr < 4; rr++) {
        int r = lr + rr*16;
        float4 qv = *(const float4*)&Qg[(size_t)(i0 + r)*DK_ + lc];
        const float4 vb = *(const float4*)&v_bias[h*DK_ + lc];
        qv.x += vb.x; qv.y += vb.y; qv.z += vb.z; qv.w += vb.w;
        Qd[r*66 + lc + 0] = make_float2(qv.x, qv.x);
        Qd[r*66 + lc + 1] = make_float2(qv.y, qv.y);
        Qd[r*66 + lc + 2] = make_float2(qv.z, qv.z);
        Qd[r*66 + lc + 3] = make_float2(qv.w, qv.w);
    }
#pragma unroll
    for (int rr = 0; rr < 8; rr++) {      // P rows 0..127 transposed [d][k]
        int r = lr + rr*16;
        float4 pv = *(const float4*)&Pg[(size_t)(k0 + r)*DK_ + lc];
        Pt[(lc + 0)*132 + r] = pv.x;
        Pt[(lc + 1)*132 + r] = pv.y;
        Pt[(lc + 2)*132 + r] = pv.z;
        Pt[(lc + 3)*132 + r] = pv.w;
    }
    __syncthreads();

    u64 acc[4][4];
#pragma unroll
    for (int i = 0; i < 4; i++)
#pragma unroll
        for (int j = 0; j < 4; j++) acc[i][j] = 0ull;

#pragma unroll 2
    for (int d = 0; d < 64; d += 2) {
        ulonglong2 av2[4];
#pragma unroll
        for (int i = 0; i < 4; i++)
            av2[i] = *(const ulonglong2*)&Qd[(ty4 + i)*66 + d];
        ulonglong2 b00 = *(const ulonglong2*)&Pt[d*132 + tx*4];
        ulonglong2 b01 = *(const ulonglong2*)&Pt[d*132 + 64 + tx*4];
        ulonglong2 b10 = *(const ulonglong2*)&Pt[(d+1)*132 + tx*4];
        ulonglong2 b11 = *(const ulonglong2*)&Pt[(d+1)*132 + 64 + tx*4];
#pragma unroll
        for (int i = 0; i < 4; i++) {
            fma2(acc[i][0], av2[i].x, b00.x);
            fma2(acc[i][1], av2[i].x, b00.y);
            fma2(acc[i][2], av2[i].x, b01.x);
            fma2(acc[i][3], av2[i].x, b01.y);
            fma2(acc[i][0], av2[i].y, b10.x);
            fma2(acc[i][1], av2[i].y, b10.y);
            fma2(acc[i][2], av2[i].y, b11.x);
            fma2(acc[i][3], av2[i].y, b11.y);
        }
    }

    float* Ao = Ag0 + (size_t)bh * S_ * S_;
#pragma unroll
    for (int i = 0; i < 4; i++)
#pragma unroll
        for (int g = 0; g < 2; g++) {
            float2 v0 = unp(acc[i][g*2]);
            float2 v1 = unp(acc[i][g*2 + 1]);
            *(float4*)&Ao[(size_t)(i0 + ty4 + i)*S_ + k0 + g*64 + tx*4] =
                make_float4(v0.x, v0.y, v1.x, v1.y);
        }
}

// ---------------------------------------------------------------------------
// Fused flash attention. BM=64, BN=128 per iter (R5 structure), LDS.128
// inner loops (R6 style).  Cols per thread: g*64 + tx*4, g = 0,1.
// smem: Qd[64*66]f2 33792 + U[64*132] 33792 + Vs[128*64] 32768 = 100352 B.
// ---------------------------------------------------------------------------
__global__ __launch_bounds__(256, 2) void flash_kernel(
    const float* __restrict__ Qg0, const float* __restrict__ Kg0,
    const float* __restrict__ Vg0, const float* __restrict__ Ag0,
    const float* __restrict__ u_bias, float* __restrict__ ctx)
{
    extern __shared__ float sm[];
    float2* Qd = (float2*)sm;          // [64*66] float2 dup(Q+u)
    float*  U  = sm + 2*64*66;         // [64*132]: Kt [d][col] / p [row][col]
    float*  Vs = U + 64*132;           // [128*64]

    const int tid = threadIdx.x;
    const int ty4 = (tid >> 4) * 4;
    const int tx  = tid & 15;
    const int i0 = blockIdx.x * 64;
    const int h = blockIdx.y, b = blockIdx.z;
    const int bh = b*H_ + h;
    const float* Qg = Qg0 + (size_t)bh * S_ * DK_;
    const float* Kg = Kg0 + (size_t)bh * S_ * DK_;
    const float* Vg = Vg0 + (size_t)bh * S_ * DK_;
    const float* Ag = Ag0 + (size_t)bh * S_ * S_;

    const int lr = tid >> 4;
    const int lc = (tid & 15) * 4;
#pragma unroll
    for (int rr = 0; rr < 4; rr++) {
        int r = lr + rr*16;
        float4 qv = *(const float4*)&Qg[(size_t)(i0 + r)*DK_ + lc];
        const float4 ub = *(const float4*)&u_bias[h*DK_ + lc];
        qv.x += ub.x; qv.y += ub.y; qv.z += ub.z; qv.w += ub.w;
        Qd[r*66 + lc + 0] = make_float2(qv.x, qv.x);
        Qd[r*66 + lc + 1] = make_float2(qv.y, qv.y);
        Qd[r*66 + lc + 2] = make_float2(qv.z, qv.z);
        Qd[r*66 + lc + 3] = make_float2(qv.w, qv.w);
    }

    float m[4], l[4];
    u64 O[4][2];
#pragma unroll
    for (int i = 0; i < 4; i++) {
        m[i] = -3.0e38f; l[i] = 0.f;
        O[i][0] = 0ull; O[i][1] = 0ull;
    }

    for (int jt = 0; jt < S_/128; jt++) {
        const int j0 = jt * 128;
        __syncthreads();   // previous iter's U/Vs reads complete
#pragma unroll
        for (int rr = 0; rr < 8; rr++) {   // K transposed into U, V row-major
            int r = lr + rr*16;
            float4 kv = *(const float4*)&Kg[(size_t)(j0 + r)*DK_ + lc];
            U[(lc + 0)*132 + r] = kv.x;
            U[(lc + 1)*132 + r] = kv.y;
            U[(lc + 2)*132 + r] = kv.z;
            U[(lc + 3)*132 + r] = kv.w;
            *(float4*)&Vs[r*64 + lc] =
                *(const float4*)&Vg[(size_t)(j0 + r)*DK_ + lc];
        }

        // ---- prefetch shifted-A gather (independent of score GEMM) ----
        // shift(A)[i,j]: A[i,S-1-i+j] (j<=i); 0 (j==i+1); A[i+1,j-i-2] (j>=i+2)
        float ap[4][8];
#pragma unroll
        for (int i = 0; i < 4; i++) {
            const int gi = i0 + ty4 + i;
            const size_t base = (size_t)gi * (S_ - 1);
#pragma unroll
            for (int g = 0; g < 2; g++)
#pragma unroll
                for (int q = 0; q < 4; q++) {
                    const int gj = j0 + g*64 + tx*4 + q;
                    const size_t idx =
                        base + gj + ((gj <= gi + 1) ? (S_ - 1) : (S_ - 2));
                    float a = __ldg(&Ag[idx]);
                    ap[i][g*4 + q] = (gj == gi + 1) ? 0.f : a;
                }
        }
        __syncthreads();

        // ---- content scores: (Q+u) . K  (LDS.128 both operands) ----
        u64 acc[4][4];
#pragma unroll
        for (int i = 0; i < 4; i++)
#pragma unroll
            for (int j = 0; j < 4; j++) acc[i][j] = 0ull;
#pragma unroll 4
        for (int d = 0; d < 64; d += 2) {
            ulonglong2 av2[4];
#pragma unroll
            for (int i = 0; i < 4; i++)
                av2[i] = *(const ulonglong2*)&Qd[(ty4 + i)*66 + d];
            ulonglong2 b00 = *(const ulonglong2*)&U[d*132 + tx*4];
            ulonglong2 b01 = *(const ulonglong2*)&U[d*132 + 64 + tx*4];
            ulonglong2 b10 = *(const ulonglong2*)&U[(d+1)*132 + tx*4];
            ulonglong2 b11 = *(const ulonglong2*)&U[(d+1)*132 + 64 + tx*4];
#pragma unroll
            for (int i = 0; i < 4; i++) {
                fma2(acc[i][0], av2[i].x, b00.x);
                fma2(acc[i][1], av2[i].x, b00.y);
                fma2(acc[i][2], av2[i].x, b01.x);
                fma2(acc[i][3], av2[i].x, b01.y);
                fma2(acc[i][0], av2[i].y, b10.x);
                fma2(acc[i][1], av2[i].y, b10.y);
                fma2(acc[i][2], av2[i].y, b11.x);
                fma2(acc[i][3], av2[i].y, b11.y);
            }
        }

        // ---- combine pos score, online softmax ----
        float ps[4][8];
#pragma unroll
        for (int i = 0; i < 4; i++) {
            float rmax = -3.0e38f;
#pragma unroll
            for (int g = 0; g < 2; g++) {
                float2 s0 = unp(acc[i][g*2]);
                float2 s1 = unp(acc[i][g*2 + 1]);
                ps[i][g*4 + 0] = (s0.x + ap[i][g*4 + 0]) * SCALE_;
                ps[i][g*4 + 1] = (s0.y + ap[i][g*4 + 1]) * SCALE_;
                ps[i][g*4 + 2] = (s1.x + ap[i][g*4 + 2]) * SCALE_;
                ps[i][g*4 + 3] = (s1.y + ap[i][g*4 + 3]) * SCALE_;
#pragma unroll
                for (int q = 0; q < 4; q++)
                    rmax = fmaxf(rmax, ps[i][g*4 + q]);
            }
#pragma unroll
            for (int o = 8; o >= 1; o >>= 1)
                rmax = fmaxf(rmax, __shfl_xor_sync(0xffffffffu, rmax, o));
            const float mnew  = fmaxf(m[i], rmax);
            const float alpha = __expf(m[i] - mnew);
            float rsum = 0.f;
#pragma unroll
            for (int jj = 0; jj < 8; jj++) {
                float e = __expf(ps[i][jj] - mnew);
                ps[i][jj] = e;
                rsum += e;
            }
#pragma unroll
            for (int o = 8; o >= 1; o >>= 1)
                rsum += __shfl_xor_sync(0xffffffffu, rsum, o);
            l[i] = l[i]*alpha + rsum;
            m[i] = mnew;
            const u64 al = dup2(alpha);
            O[i][0] = mul2(O[i][0], al);
            O[i][1] = mul2(O[i][1], al);
        }

        __syncthreads();   // Kt reads done before overwriting U with p
#pragma unroll
        for (int i = 0; i < 4; i++)
#pragma unroll
            for (int g = 0; g < 2; g++)
                *(float4*)&U[(ty4 + i)*132 + g*64 + tx*4] =
                    make_float4(ps[i][g*4 + 0], ps[i][g*4 + 1],
                                ps[i][g*4 + 2], ps[i][g*4 + 3]);
        __syncthreads();

        // ---- O += p @ V  (float4 p-quads, LDS.64 V) ----
#pragma unroll 2
        for (int j = 0; j < 128; j += 4) {
            float4 pq[4];
#pragma unroll
            for (int i = 0; i < 4; i++)
                pq[i] = *(const float4*)&U[(ty4 + i)*132 + j];
            u64 v00 = *(const u64*)&Vs[(j+0)*64 + tx*2];
            u64 v01 = *(const u64*)&Vs[(j+0)*64 + 32 + tx*2];
            u64 v10 = *(const u64*)&Vs[(j+1)*64 + tx*2];
            u64 v11 = *(const u64*)&Vs[(j+1)*64 + 32 + tx*2];
            u64 v20 = *(const u64*)&Vs[(j+2)*64 + tx*2];
            u64 v21 = *(const u64*)&Vs[(j+2)*64 + 32 + tx*2];
            u64 v30 = *(const u64*)&Vs[(j+3)*64 + tx*2];
            u64 v31 = *(const u64*)&Vs[(j+3)*64 + 32 + tx*2];
#pragma unroll
            for (int i = 0; i < 4; i++) {
                u64 a;
                a = dup2(pq[i].x); fma2(O[i][0], a, v00); fma2(O[i][1], a, v01);
                a = dup2(pq[i].y); fma2(O[i][0], a, v10); fma2(O[i][1], a, v11);
                a = dup2(pq[i].z); fma2(O[i][0], a, v20); fma2(O[i][1], a, v21);
                a = dup2(pq[i].w); fma2(O[i][0], a, v30); fma2(O[i][1], a, v31);
            }
        }
    }

    // epilogue: normalize, write context as [B,S,H*DK]
#pragma unroll
    for (int i = 0; i < 4; i++) {
        const int gi = i0 + ty4 + i;
        const float inv = 1.0f / l[i];
        float2 o0 = unp(O[i][0]); o0.x *= inv; o0.y *= inv;
        float2 o1 = unp(O[i][1]); o1.x *= inv; o1.y *= inv;
        float* dst = &ctx[((size_t)b*S_ + gi)*DM_ + h*DK_];
        *(float2*)&dst[tx*2]      = o0;
        *(float2*)&dst[32 + tx*2] = o1;
    }
}

// ---------------------------------------------------------------------------
extern "C" void kernel_launch(void* const* d_in, const int* in_sizes, int n_in,
                              void* d_out, int out_size)
{
    (void)in_sizes; (void)n_in; (void)out_size;
    const float* inputs  = (const float*)d_in[0];
    const float* pos_enc = (const float*)d_in[1];
    const float* W_q     = (const float*)d_in[2];
    const float* W_k     = (const float*)d_in[3];
    const float* W_v     = (const float*)d_in[4];
    const float* W_o     = (const float*)d_in[5];
    const float* W_pos   = (const float*)d_in[6];
    const float* u_b     = (const float*)d_in[7];
    const float* v_b     = (const float*)d_in[8];
    float* out = (float*)d_out;

    float *qp, *kp, *vp, *pp, *ap, *cp;
    cudaGetSymbolAddress((void**)&qp, g_Q);
    cudaGetSymbolAddress((void**)&kp, g_K);
    cudaGetSymbolAddress((void**)&vp, g_V);
    cudaGetSymbolAddress((void**)&pp, g_P);
    cudaGetSymbolAddress((void**)&ap, g_A);
    cudaGetSymbolAddress((void**)&cp, g_ctx);

    const int POSA_SMEM  = (2*64*66 + 64*132) * (int)sizeof(float);           // 67584
    const int FLASH_SMEM = (2*64*66 + 64*132 + 128*64) * (int)sizeof(float);  // 100352
    cudaFuncSetAttribute(posA_kernel,
                         cudaFuncAttributeMaxDynamicSharedMemorySize, POSA_SMEM);
    cudaFuncSetAttribute(flash_kernel,
                         cudaFuncAttributeMaxDynamicSharedMemorySize, FLASH_SMEM);
    cudaFuncSetAttribute(posA_kernel,
                         cudaFuncAttributePreferredSharedMemoryCarveout, 100);
    cudaFuncSetAttribute(flash_kernel,
                         cudaFuncAttributePreferredSharedMemoryCarveout, 100);

    const dim3 thr(256);
    // fused Q/K/V projections (head-split layout)
    qkv_kernel<<<dim3(128, 4, 3), thr>>>(inputs, W_q, W_k, W_v, qp, kp, vp);
    // pos projection
    gemm512_kernel<1><<<dim3(32, 4), thr>>>(pos_enc, W_pos, pp);
    // pos matrix A = (Q+v) @ P^T per (b,h)
    posA_kernel<<<dim3(16, 32, 32), thr, POSA_SMEM>>>(qp, pp, v_b, ap);
    // fused attention -> g_ctx
    flash_kernel<<<dim3(32, 8, 4), thr, FLASH_SMEM>>>(qp, kp, vp, ap, u_b, cp);
    // output projection: ctx @ W_o -> out
    gemm512_kernel<0><<<dim3(128, 4), thr>>>(cp, W_o, out);
}

// round 13
// speedup vs baseline: 1.0469x; 1.0155x over previous
#include <cuda_runtime.h>

#define B_  4
#define S_  2048
#define DM_ 512
#define H_  8
#define DK_ 64
#define SCALE_ 0.125f

typedef unsigned long long u64;

__device__ __forceinline__ void fma2(u64 &c, u64 a, u64 b) {
    asm("fma.rn.f32x2 %0, %1, %2, %0;" : "+l"(c) : "l"(a), "l"(b));
}
__device__ __forceinline__ u64 mul2(u64 a, u64 b) {
    u64 r; asm("mul.rn.f32x2 %0, %1, %2;" : "=l"(r) : "l"(a), "l"(b)); return r;
}
__device__ __forceinline__ u64 dup2(float a) {
    u64 r; asm("mov.b64 %0, {%1, %1};" : "=l"(r) : "f"(a)); return r;
}
__device__ __forceinline__ float2 unp(u64 v) {
    float2 f; asm("mov.b64 {%0, %1}, %2;" : "=f"(f.x), "=f"(f.y) : "l"(v)); return f;
}

// ---------------- scratch (device globals: allocation-free rule) -------------
__device__ float g_Q[B_*H_*S_*DK_];
__device__ float g_K[B_*H_*S_*DK_];
__device__ float g_V[B_*H_*S_*DK_];
__device__ float g_P[H_*S_*DK_];
__device__ float g_A[(size_t)B_*H_*S_*S_];     // holds SCALE * (Q+v)·P^T
__device__ float g_ctx[B_*S_*DM_];

// ---------------------------------------------------------------------------
// GEMM body: C = X[.,512] @ W[512,512], 64x128 tile, double-buffered, f32x2.
// ---------------------------------------------------------------------------
template<int SPLIT>
__device__ __forceinline__ void gemm_body(
    const float* __restrict__ X, const float* __restrict__ W,
    float* __restrict__ out, int m0, int n0,
    float2 (*As2)[64*18], float (*Bs)[16*128])
{
    const int tid = threadIdx.x;
    const int ty4 = (tid >> 4) * 4;
    const int tx  = tid & 15;
    const int ar = tid >> 2, ac = (tid & 3) * 4;
    const int br = tid >> 4, bc = (tid & 15) * 8;
    const float* Xp = &X[(size_t)(m0 + ar)*512 + ac];
    const float* Wp = &W[(size_t)br*512 + n0 + bc];

    u64 acc[4][4];
#pragma unroll
    for (int i = 0; i < 4; i++)
#pragma unroll
        for (int j = 0; j < 4; j++) acc[i][j] = 0ull;

    {
        float4 a4  = *(const float4*)Xp;
        float4 b40 = *(const float4*)&Wp[0];
        float4 b41 = *(const float4*)&Wp[4];
        As2[0][ar*18 + ac + 0] = make_float2(a4.x, a4.x);
        As2[0][ar*18 + ac + 1] = make_float2(a4.y, a4.y);
        As2[0][ar*18 + ac + 2] = make_float2(a4.z, a4.z);
        As2[0][ar*18 + ac + 3] = make_float2(a4.w, a4.w);
        *(float4*)&Bs[0][br*128 + bc]     = b40;
        *(float4*)&Bs[0][br*128 + bc + 4] = b41;
    }
    __syncthreads();

    for (int k0 = 0; k0 < 32; k0++) {
        const int cur = k0 & 1;
        float4 na, nb0, nb1;
        if (k0 < 31) {
            na  = *(const float4*)(Xp + (k0 + 1)*16);
            nb0 = *(const float4*)(Wp + (size_t)(k0 + 1)*16*512);
            nb1 = *(const float4*)(Wp + (size_t)(k0 + 1)*16*512 + 4);
        }
#pragma unroll
        for (int kk = 0; kk < 16; kk += 2) {
            ulonglong2 av2[4];
#pragma unroll
            for (int i = 0; i < 4; i++)
                av2[i] = *(const ulonglong2*)&As2[cur][(ty4 + i)*18 + kk];
            ulonglong2 b00 = *(const ulonglong2*)&Bs[cur][kk*128 + tx*4];
            ulonglong2 b01 = *(const ulonglong2*)&Bs[cur][kk*128 + 64 + tx*4];
            ulonglong2 b10 = *(const ulonglong2*)&Bs[cur][(kk+1)*128 + tx*4];
            ulonglong2 b11 = *(const ulonglong2*)&Bs[cur][(kk+1)*128 + 64 + tx*4];
#pragma unroll
            for (int i = 0; i < 4; i++) {
                fma2(acc[i][0], av2[i].x, b00.x);
                fma2(acc[i][1], av2[i].x, b00.y);
                fma2(acc[i][2], av2[i].x, b01.x);
                fma2(acc[i][3], av2[i].x, b01.y);
                fma2(acc[i][0], av2[i].y, b10.x);
                fma2(acc[i][1], av2[i].y, b10.y);
                fma2(acc[i][2], av2[i].y, b11.x);
                fma2(acc[i][3], av2[i].y, b11.y);
            }
        }
        if (k0 < 31) {
            const int nxt = cur ^ 1;
            As2[nxt][ar*18 + ac + 0] = make_float2(na.x, na.x);
            As2[nxt][ar*18 + ac + 1] = make_float2(na.y, na.y);
            As2[nxt][ar*18 + ac + 2] = make_float2(na.z, na.z);
            As2[nxt][ar*18 + ac + 3] = make_float2(na.w, na.w);
            *(float4*)&Bs[nxt][br*128 + bc]     = nb0;
            *(float4*)&Bs[nxt][br*128 + bc + 4] = nb1;
        }
        __syncthreads();
    }

#pragma unroll
    for (int i = 0; i < 4; i++) {
        const int mm = m0 + ty4 + i;
#pragma unroll
        for (int g = 0; g < 2; g++) {
            const int nn = n0 + g*64 + tx*4;
            float2 v0 = unp(acc[i][g*2]);
            float2 v1 = unp(acc[i][g*2 + 1]);
            float4 o4 = make_float4(v0.x, v0.y, v1.x, v1.y);
            if (SPLIT) {
                int bb = mm >> 11, ss = mm & 2047;
                int hh = nn >> 6,  dd = nn & 63;
                *(float4*)&out[((size_t)(bb*H_ + hh)*S_ + ss)*DK_ + dd] = o4;
            } else {
                *(float4*)&out[(size_t)mm*512 + nn] = o4;
            }
        }
    }
}

template<int SPLIT>
__global__ __launch_bounds__(256, 3) void gemm512_kernel(
    const float* __restrict__ X, const float* __restrict__ W,
    float* __restrict__ out)
{
    __shared__ float2 As2[2][64*18];
    __shared__ float  Bs[2][16*128];
    gemm_body<SPLIT>(X, W, out, blockIdx.x*64, blockIdx.y*128, As2, Bs);
}

__global__ __launch_bounds__(256, 3) void qkv_kernel(
    const float* __restrict__ X,
    const float* __restrict__ Wq, const float* __restrict__ Wk,
    const float* __restrict__ Wv,
    float* __restrict__ oq, float* __restrict__ ok, float* __restrict__ ov)
{
    __shared__ float2 As2[2][64*18];
    __shared__ float  Bs[2][16*128];
    const float* W = (blockIdx.z == 0) ? Wq : (blockIdx.z == 1) ? Wk : Wv;
    float* out     = (blockIdx.z == 0) ? oq : (blockIdx.z == 1) ? ok : ov;
    gemm_body<1>(X, W, out, blockIdx.x*64, blockIdx.y*128, As2, Bs);
}

// ---------------------------------------------------------------------------
// A[bh,i,k] = SCALE * sum_d (Q[bh,i,d]+v_bias[h,d]) * P[h,k,d].
// 64x128 tile, K=64.  SCALE folded into the Q operand.
// ---------------------------------------------------------------------------
__global__ __launch_bounds__(256, 3) void posA_kernel(
    const float* __restrict__ Qg0, const float* __restrict__ Pg0,
    const float* __restrict__ v_bias, float* __restrict__ Ag0)
{
    extern __shared__ float sm[];
    float2* Qd = (float2*)sm;          // [64*66] float2
    float*  Pt = sm + 2*64*66;         // [64*132]

    const int tid = threadIdx.x;
    const int ty4 = (tid >> 4) * 4;
    const int tx  = tid & 15;
    const int k0 = blockIdx.x * 128;
    const int i0 = blockIdx.y * 64;
    const int bh = blockIdx.z;
    const int h  = bh & 7;
    const float* Qg = Qg0 + (size_t)bh * S_ * DK_;
    const float* Pg = Pg0 + (size_t)h  * S_ * DK_;

    const int lr = tid >> 4;
    const int lc = (tid & 15) * 4;
#pragma unroll
    for (int rr = 0; rr < 4; rr++) {
        int r = lr + rr*16;
        float4 qv = *(const float4*)&Qg[(size_t)(i0 + r)*DK_ + lc];
        const float4 vb = *(const float4*)&v_bias[h*DK_ + lc];
        float qx = (qv.x + vb.x) * SCALE_;
        float qy = (qv.y + vb.y) * SCALE_;
        float qz = (qv.z + vb.z) * SCALE_;
        float qw = (qv.w + vb.w) * SCALE_;
        Qd[r*66 + lc + 0] = make_float2(qx, qx);
        Qd[r*66 + lc + 1] = make_float2(qy, qy);
        Qd[r*66 + lc + 2] = make_float2(qz, qz);
        Qd[r*66 + lc + 3] = make_float2(qw, qw);
    }
#pragma unroll
    for (int rr = 0; rr < 8; rr++) {      // P rows 0..127 transposed [d][k]
        int r = lr + rr*16;
        float4 pv = *(const float4*)&Pg[(size_t)(k0 + r)*DK_ + lc];
        Pt[(lc + 0)*132 + r] = pv.x;
        Pt[(lc + 1)*132 + r] = pv.y;
        Pt[(lc + 2)*132 + r] = pv.z;
        Pt[(lc + 3)*132 + r] = pv.w;
    }
    __syncthreads();

    u64 acc[4][4];
#pragma unroll
    for (int i = 0; i < 4; i++)
#pragma unroll
        for (int j = 0; j < 4; j++) acc[i][j] = 0ull;

#pragma unroll 2
    for (int d = 0; d < 64; d += 2) {
        ulonglong2 av2[4];
#pragma unroll
        for (int i = 0; i < 4; i++)
            av2[i] = *(const ulonglong2*)&Qd[(ty4 + i)*66 + d];
        ulonglong2 b00 = *(const ulonglong2*)&Pt[d*132 + tx*4];
        ulonglong2 b01 = *(const ulonglong2*)&Pt[d*132 + 64 + tx*4];
        ulonglong2 b10 = *(const ulonglong2*)&Pt[(d+1)*132 + tx*4];
        ulonglong2 b11 = *(const ulonglong2*)&Pt[(d+1)*132 + 64 + tx*4];
#pragma unroll
        for (int i = 0; i < 4; i++) {
            fma2(acc[i][0], av2[i].x, b00.x);
            fma2(acc[i][1], av2[i].x, b00.y);
            fma2(acc[i][2], av2[i].x, b01.x);
            fma2(acc[i][3], av2[i].x, b01.y);
            fma2(acc[i][0], av2[i].y, b10.x);
            fma2(acc[i][1], av2[i].y, b10.y);
            fma2(acc[i][2], av2[i].y, b11.x);
            fma2(acc[i][3], av2[i].y, b11.y);
        }
    }

    float* Ao = Ag0 + (size_t)bh * S_ * S_;
#pragma unroll
    for (int i = 0; i < 4; i++)
#pragma unroll
        for (int g = 0; g < 2; g++) {
            float2 v0 = unp(acc[i][g*2]);
            float2 v1 = unp(acc[i][g*2 + 1]);
            *(float4*)&Ao[(size_t)(i0 + ty4 + i)*S_ + k0 + g*64 + tx*4] =
                make_float4(v0.x, v0.y, v1.x, v1.y);
        }
}

// ---------------------------------------------------------------------------
// Fused flash attention (R5 structure = best measured). BM=64, BN=128, f32x2.
// Q pre-scaled by SCALE; A already pre-scaled -> ps = acc + ap (no mul).
// p-staging round trip is half-warp-local -> __syncwarp instead of barrier.
// smem: Qd 33280 + U 33280 + Vs 32768 = 99328 B (2 blocks/SM).
// ---------------------------------------------------------------------------
__global__ __launch_bounds__(256, 2) void flash_kernel(
    const float* __restrict__ Qg0, const float* __restrict__ Kg0,
    const float* __restrict__ Vg0, const float* __restrict__ Ag0,
    const float* __restrict__ u_bias, float* __restrict__ ctx)
{
    extern __shared__ float sm[];
    float2* Qd = (float2*)sm;          // [64*65] float2 dup((Q+u)*SCALE)
    float*  U  = sm + 2*64*65;         // [64*130]: Kt [d][col] / p [row][col]
    float*  Vs = U + 64*130;           // [128*64]

    const int tid = threadIdx.x;
    const int ty4 = (tid >> 4) * 4;
    const int tx  = tid & 15;
    const int i0 = blockIdx.x * 64;
    const int h = blockIdx.y, b = blockIdx.z;
    const int bh = b*H_ + h;
    const float* Qg = Qg0 + (size_t)bh * S_ * DK_;
    const float* Kg = Kg0 + (size_t)bh * S_ * DK_;
    const float* Vg = Vg0 + (size_t)bh * S_ * DK_;
    const float* Ag = Ag0 + (size_t)bh * S_ * S_;

    const int lr = tid >> 4;
    const int lc = (tid & 15) * 4;
#pragma unroll
    for (int rr = 0; rr < 4; rr++) {
        int r = lr + rr*16;
        float4 qv = *(const float4*)&Qg[(size_t)(i0 + r)*DK_ + lc];
        const float4 ub = *(const float4*)&u_bias[h*DK_ + lc];
        float qx = (qv.x + ub.x) * SCALE_;
        float qy = (qv.y + ub.y) * SCALE_;
        float qz = (qv.z + ub.z) * SCALE_;
        float qw = (qv.w + ub.w) * SCALE_;
        Qd[r*65 + lc + 0] = make_float2(qx, qx);
        Qd[r*65 + lc + 1] = make_float2(qy, qy);
        Qd[r*65 + lc + 2] = make_float2(qz, qz);
        Qd[r*65 + lc + 3] = make_float2(qw, qw);
    }

    float m[4], l[4];
    u64 O[4][2];
#pragma unroll
    for (int i = 0; i < 4; i++) {
        m[i] = -3.0e38f; l[i] = 0.f;
        O[i][0] = 0ull; O[i][1] = 0ull;
    }

    for (int jt = 0; jt < S_/128; jt++) {
        const int j0 = jt * 128;
        __syncthreads();   // prev iter's U(p)/Vs reads done (covers Qd @jt=0)
#pragma unroll
        for (int rr = 0; rr < 8; rr++) {   // K transposed into U, V row-major
            int r = lr + rr*16;
            float4 kv = *(const float4*)&Kg[(size_t)(j0 + r)*DK_ + lc];
            U[(lc + 0)*130 + r] = kv.x;
            U[(lc + 1)*130 + r] = kv.y;
            U[(lc + 2)*130 + r] = kv.z;
            U[(lc + 3)*130 + r] = kv.w;
            *(float4*)&Vs[r*64 + lc] =
                *(const float4*)&Vg[(size_t)(j0 + r)*DK_ + lc];
        }

        // ---- prefetch shifted-A gather (independent of score GEMM) ----
        float ap[4][8];
#pragma unroll
        for (int i = 0; i < 4; i++) {
            const int gi = i0 + ty4 + i;
            const size_t base = (size_t)gi * (S_ - 1);
#pragma unroll
            for (int j = 0; j < 4; j++)
#pragma unroll
                for (int q = 0; q < 2; q++) {
                    const int gj = j0 + j*32 + tx*2 + q;
                    const size_t idx =
                        base + gj + ((gj <= gi + 1) ? (S_ - 1) : (S_ - 2));
                    float a = __ldg(&Ag[idx]);
                    ap[i][j*2 + q] = (gj == gi + 1) ? 0.f : a;
                }
        }
        __syncthreads();

        // ---- content scores: ((Q+u)*SCALE) . K ----
        u64 acc[4][4];
#pragma unroll
        for (int i = 0; i < 4; i++)
#pragma unroll
            for (int j = 0; j < 4; j++) acc[i][j] = 0ull;
#pragma unroll 4
        for (int d = 0; d < 64; d++) {
            u64 av[4], bv[4];
#pragma unroll
            for (int i = 0; i < 4; i++)
                av[i] = *(const u64*)&Qd[(ty4 + i)*65 + d];
#pragma unroll
            for (int j = 0; j < 4; j++)
                bv[j] = *(const u64*)&U[d*130 + j*32 + tx*2];
#pragma unroll
            for (int i = 0; i < 4; i++)
#pragma unroll
                for (int j = 0; j < 4; j++)
                    fma2(acc[i][j], av[i], bv[j]);
        }

        // ---- combine prescaled pos score, online softmax ----
        float ps[4][8];
#pragma unroll
        for (int i = 0; i < 4; i++) {
            float rmax = -3.0e38f;
#pragma unroll
            for (int j = 0; j < 4; j++) {
                float2 sc = unp(acc[i][j]);
                float s0 = sc.x + ap[i][j*2];
                float s1 = sc.y + ap[i][j*2 + 1];
                ps[i][j*2]     = s0;
                ps[i][j*2 + 1] = s1;
                rmax = fmaxf(rmax, fmaxf(s0, s1));
            }
#pragma unroll
            for (int o = 8; o >= 1; o >>= 1)
                rmax = fmaxf(rmax, __shfl_xor_sync(0xffffffffu, rmax, o));
            const float mnew  = fmaxf(m[i], rmax);
            const float alpha = __expf(m[i] - mnew);
            float rsum = 0.f;
#pragma unroll
            for (int jj = 0; jj < 8; jj++) {
                float e = __expf(ps[i][jj] - mnew);
                ps[i][jj] = e;
                rsum += e;
            }
#pragma unroll
            for (int o = 8; o >= 1; o >>= 1)
                rsum += __shfl_xor_sync(0xffffffffu, rsum, o);
            l[i] = l[i]*alpha + rsum;
            m[i] = mnew;
            const u64 al = dup2(alpha);
            O[i][0] = mul2(O[i][0], al);
            O[i][1] = mul2(O[i][1], al);
        }

        __syncthreads();   // ALL warps done reading Kt before U <- p
#pragma unroll
        for (int i = 0; i < 4; i++)
#pragma unroll
            for (int j = 0; j < 4; j++)
                *(float2*)&U[(ty4 + i)*130 + j*32 + tx*2] =
                    make_float2(ps[i][j*2], ps[i][j*2 + 1]);
        __syncwarp();      // p rows are written & read by the same half-warp

        // ---- O += p @ V ----
#pragma unroll 2
        for (int j = 0; j < 128; j++) {
            u64 a2[4];
#pragma unroll
            for (int i = 0; i < 4; i++)
                a2[i] = dup2(U[(ty4 + i)*130 + j]);
            u64 bv0 = *(const u64*)&Vs[j*64 + tx*2];
            u64 bv1 = *(const u64*)&Vs[j*64 + 32 + tx*2];
#pragma unroll
            for (int i = 0; i < 4; i++) {
                fma2(O[i][0], a2[i], bv0);
                fma2(O[i][1], a2[i], bv1);
            }
        }
    }

    // epilogue: normalize, write context as [B,S,H*DK]
#pragma unroll
    for (int i = 0; i < 4; i++) {
        const int gi = i0 + ty4 + i;
        const float inv = 1.0f / l[i];
        float2 o0 = unp(O[i][0]); o0.x *= inv; o0.y *= inv;
        float2 o1 = unp(O[i][1]); o1.x *= inv; o1.y *= inv;
        float* dst = &ctx[((size_t)b*S_ + gi)*DM_ + h*DK_];
        *(float2*)&dst[tx*2]      = o0;
        *(float2*)&dst[32 + tx*2] = o1;
    }
}

// ---------------------------------------------------------------------------
extern "C" void kernel_launch(void* const* d_in, const int* in_sizes, int n_in,
                              void* d_out, int out_size)
{
    (void)in_sizes; (void)n_in; (void)out_size;
    const float* inputs  = (const float*)d_in[0];
    const float* pos_enc = (const float*)d_in[1];
    const float* W_q     = (const float*)d_in[2];
    const float* W_k     = (const float*)d_in[3];
    const float* W_v     = (const float*)d_in[4];
    const float* W_o     = (const float*)d_in[5];
    const float* W_pos   = (const float*)d_in[6];
    const float* u_b     = (const float*)d_in[7];
    const float* v_b     = (const float*)d_in[8];
    float* out = (float*)d_out;

    float *qp, *kp, *vp, *pp, *ap, *cp;
    cudaGetSymbolAddress((void**)&qp, g_Q);
    cudaGetSymbolAddress((void**)&kp, g_K);
    cudaGetSymbolAddress((void**)&vp, g_V);
    cudaGetSymbolAddress((void**)&pp, g_P);
    cudaGetSymbolAddress((void**)&ap, g_A);
    cudaGetSymbolAddress((void**)&cp, g_ctx);

    const int POSA_SMEM  = (2*64*66 + 64*132) * (int)sizeof(float);           // 67584
    const int FLASH_SMEM = (2*64*65 + 64*130 + 128*64) * (int)sizeof(float);  // 99328
    cudaFuncSetAttribute(posA_kernel,
                         cudaFuncAttributeMaxDynamicSharedMemorySize, POSA_SMEM);
    cudaFuncSetAttribute(flash_kernel,
                         cudaFuncAttributeMaxDynamicSharedMemorySize, FLASH_SMEM);
    cudaFuncSetAttribute(posA_kernel,
                         cudaFuncAttributePreferredSharedMemoryCarveout, 100);
    cudaFuncSetAttribute(flash_kernel,
                         cudaFuncAttributePreferredSharedMemoryCarveout, 100);

    const dim3 thr(256);
    // fused Q/K/V projections (head-split layout)
    qkv_kernel<<<dim3(128, 4, 3), thr>>>(inputs, W_q, W_k, W_v, qp, kp, vp);
    // pos projection
    gemm512_kernel<1><<<dim3(32, 4), thr>>>(pos_enc, W_pos, pp);
    // pos matrix A = SCALE*(Q+v) @ P^T per (b,h)
    posA_kernel<<<dim3(16, 32, 32), thr, POSA_SMEM>>>(qp, pp, v_b, ap);
    // fused attention -> g_ctx
    flash_kernel<<<dim3(32, 8, 4), thr, FLASH_SMEM>>>(qp, kp, vp, ap, u_b, cp);
    // output projection: ctx @ W_o -> out
    gemm512_kernel<0><<<dim3(128, 4), thr>>>(cp, W_o, out);
}

// round 14
// speedup vs baseline: 1.0528x; 1.0056x over previous
#include <cuda_runtime.h>

#define B_  4
#define S_  2048
#define DM_ 512
#define H_  8
#define DK_ 64
#define SCALE_ 0.125f

typedef unsigned long long u64;
typedef unsigned int u32;

__device__ __forceinline__ void fma2(u64 &c, u64 a, u64 b) {
    asm("fma.rn.f32x2 %0, %1, %2, %0;" : "+l"(c) : "l"(a), "l"(b));
}
__device__ __forceinline__ u64 mul2(u64 a, u64 b) {
    u64 r; asm("mul.rn.f32x2 %0, %1, %2;" : "=l"(r) : "l"(a), "l"(b)); return r;
}
__device__ __forceinline__ u64 dup2(float a) {
    u64 r; asm("mov.b64 %0, {%1, %1};" : "=l"(r) : "f"(a)); return r;
}
__device__ __forceinline__ float2 unp(u64 v) {
    float2 f; asm("mov.b64 {%0, %1}, %2;" : "=f"(f.x), "=f"(f.y) : "l"(v)); return f;
}
__device__ __forceinline__ u32 s2u(const void* p) {
    u32 a;
    asm("{ .reg .u64 t; cvta.to.shared.u64 t, %1; cvt.u32.u64 %0, t; }"
        : "=r"(a) : "l"(p));
    return a;
}
__device__ __forceinline__ void cpasync16(u32 sdst, const void* gsrc) {
    u64 g;
    asm("cvta.to.global.u64 %0, %1;" : "=l"(g) : "l"(gsrc));
    asm volatile("cp.async.cg.shared.global [%0], [%1], 16;"
                 :: "r"(sdst), "l"(g) : "memory");
}

// ---------------- scratch (device globals: allocation-free rule) -------------
__device__ float g_Q[B_*H_*S_*DK_];
__device__ float g_K[B_*H_*S_*DK_];
__device__ float g_V[B_*H_*S_*DK_];
__device__ float g_P[H_*S_*DK_];
__device__ float g_A[(size_t)B_*H_*S_*S_];     // PRE-SHIFTED scaled pos scores
__device__ float g_ctx[B_*S_*DM_];

// ---------------------------------------------------------------------------
// GEMM body: C = X[.,512] @ W[512,512], 64x128 tile, double-buffered, f32x2.
// ---------------------------------------------------------------------------
template<int SPLIT>
__device__ __forceinline__ void gemm_body(
    const float* __restrict__ X, const float* __restrict__ W,
    float* __restrict__ out, int m0, int n0,
    float2 (*As2)[64*18], float (*Bs)[16*128])
{
    const int tid = threadIdx.x;
    const int ty4 = (tid >> 4) * 4;
    const int tx  = tid & 15;
    const int ar = tid >> 2, ac = (tid & 3) * 4;
    const int br = tid >> 4, bc = (tid & 15) * 8;
    const float* Xp = &X[(size_t)(m0 + ar)*512 + ac];
    const float* Wp = &W[(size_t)br*512 + n0 + bc];

    u64 acc[4][4];
#pragma unroll
    for (int i = 0; i < 4; i++)
#pragma unroll
        for (int j = 0; j < 4; j++) acc[i][j] = 0ull;

    {
        float4 a4  = *(const float4*)Xp;
        float4 b40 = *(const float4*)&Wp[0];
        float4 b41 = *(const float4*)&Wp[4];
        As2[0][ar*18 + ac + 0] = make_float2(a4.x, a4.x);
        As2[0][ar*18 + ac + 1] = make_float2(a4.y, a4.y);
        As2[0][ar*18 + ac + 2] = make_float2(a4.z, a4.z);
        As2[0][ar*18 + ac + 3] = make_float2(a4.w, a4.w);
        *(float4*)&Bs[0][br*128 + bc]     = b40;
        *(float4*)&Bs[0][br*128 + bc + 4] = b41;
    }
    __syncthreads();

    for (int k0 = 0; k0 < 32; k0++) {
        const int cur = k0 & 1;
        float4 na, nb0, nb1;
        if (k0 < 31) {
            na  = *(const float4*)(Xp + (k0 + 1)*16);
            nb0 = *(const float4*)(Wp + (size_t)(k0 + 1)*16*512);
            nb1 = *(const float4*)(Wp + (size_t)(k0 + 1)*16*512 + 4);
        }
#pragma unroll
        for (int kk = 0; kk < 16; kk += 2) {
            ulonglong2 av2[4];
#pragma unroll
            for (int i = 0; i < 4; i++)
                av2[i] = *(const ulonglong2*)&As2[cur][(ty4 + i)*18 + kk];
            ulonglong2 b00 = *(const ulonglong2*)&Bs[cur][kk*128 + tx*4];
            ulonglong2 b01 = *(const ulonglong2*)&Bs[cur][kk*128 + 64 + tx*4];
            ulonglong2 b10 = *(const ulonglong2*)&Bs[cur][(kk+1)*128 + tx*4];
            ulonglong2 b11 = *(const ulonglong2*)&Bs[cur][(kk+1)*128 + 64 + tx*4];
#pragma unroll
            for (int i = 0; i < 4; i++) {
                fma2(acc[i][0], av2[i].x, b00.x);
                fma2(acc[i][1], av2[i].x, b00.y);
                fma2(acc[i][2], av2[i].x, b01.x);
                fma2(acc[i][3], av2[i].x, b01.y);
                fma2(acc[i][0], av2[i].y, b10.x);
                fma2(acc[i][1], av2[i].y, b10.y);
                fma2(acc[i][2], av2[i].y, b11.x);
                fma2(acc[i][3], av2[i].y, b11.y);
            }
        }
        if (k0 < 31) {
            const int nxt = cur ^ 1;
            As2[nxt][ar*18 + ac + 0] = make_float2(na.x, na.x);
            As2[nxt][ar*18 + ac + 1] = make_float2(na.y, na.y);
            As2[nxt][ar*18 + ac + 2] = make_float2(na.z, na.z);
            As2[nxt][ar*18 + ac + 3] = make_float2(na.w, na.w);
            *(float4*)&Bs[nxt][br*128 + bc]     = nb0;
            *(float4*)&Bs[nxt][br*128 + bc + 4] = nb1;
        }
        __syncthreads();
    }

#pragma unroll
    for (int i = 0; i < 4; i++) {
        const int mm = m0 + ty4 + i;
#pragma unroll
        for (int g = 0; g < 2; g++) {
            const int nn = n0 + g*64 + tx*4;
            float2 v0 = unp(acc[i][g*2]);
            float2 v1 = unp(acc[i][g*2 + 1]);
            float4 o4 = make_float4(v0.x, v0.y, v1.x, v1.y);
            if (SPLIT) {
                int bb = mm >> 11, ss = mm & 2047;
                int hh = nn >> 6,  dd = nn & 63;
                *(float4*)&out[((size_t)(bb*H_ + hh)*S_ + ss)*DK_ + dd] = o4;
            } else {
                *(float4*)&out[(size_t)mm*512 + nn] = o4;
            }
        }
    }
}

template<int SPLIT>
__global__ __launch_bounds__(256, 3) void gemm512_kernel(
    const float* __restrict__ X, const float* __restrict__ W,
    float* __restrict__ out)
{
    __shared__ float2 As2[2][64*18];
    __shared__ float  Bs[2][16*128];
    gemm_body<SPLIT>(X, W, out, blockIdx.x*64, blockIdx.y*128, As2, Bs);
}

__global__ __launch_bounds__(256, 3) void qkv_kernel(
    const float* __restrict__ X,
    const float* __restrict__ Wq, const float* __restrict__ Wk,
    const float* __restrict__ Wv,
    float* __restrict__ oq, float* __restrict__ ok, float* __restrict__ ov)
{
    __shared__ float2 As2[2][64*18];
    __shared__ float  Bs[2][16*128];
    const float* W = (blockIdx.z == 0) ? Wq : (blockIdx.z == 1) ? Wk : Wv;
    float* out     = (blockIdx.z == 0) ? oq : (blockIdx.z == 1) ? ok : ov;
    gemm_body<1>(X, W, out, blockIdx.x*64, blockIdx.y*128, As2, Bs);
}

// ---------------------------------------------------------------------------
// posA: computes SCALE*(Q_i+v)·P_k and stores PRE-SHIFTED:
//   element (i,k):  k >= S-1-i  -> Ashift[i][k-(S-1-i)]
//                   else (i>=1) -> Ashift[i-1][k+i+1]
//                   (i==0, k<S-1 -> dropped; diagonal j=i+1 never written,
//                    flash zero-selects it)
// ---------------------------------------------------------------------------
__global__ __launch_bounds__(256, 3) void posA_kernel(
    const float* __restrict__ Qg0, const float* __restrict__ Pg0,
    const float* __restrict__ v_bias, float* __restrict__ Ag0)
{
    extern __shared__ float sm[];
    float2* Qd = (float2*)sm;          // [64*66] float2
    float*  Pt = sm + 2*64*66;         // [64*132]

    const int tid = threadIdx.x;
    const int ty4 = (tid >> 4) * 4;
    const int tx  = tid & 15;
    const int k0 = blockIdx.x * 128;
    const int i0 = blockIdx.y * 64;
    const int bh = blockIdx.z;
    const int h  = bh & 7;
    const float* Qg = Qg0 + (size_t)bh * S_ * DK_;
    const float* Pg = Pg0 + (size_t)h  * S_ * DK_;

    const int lr = tid >> 4;
    const int lc = (tid & 15) * 4;
#pragma unroll
    for (int rr = 0; rr < 4; rr++) {
        int r = lr + rr*16;
        float4 qv = *(const float4*)&Qg[(size_t)(i0 + r)*DK_ + lc];
        const float4 vb = *(const float4*)&v_bias[h*DK_ + lc];
        float qx = (qv.x + vb.x) * SCALE_;
        float qy = (qv.y + vb.y) * SCALE_;
        float qz = (qv.z + vb.z) * SCALE_;
        float qw = (qv.w + vb.w) * SCALE_;
        Qd[r*66 + lc + 0] = make_float2(qx, qx);
        Qd[r*66 + lc + 1] = make_float2(qy, qy);
        Qd[r*66 + lc + 2] = make_float2(qz, qz);
        Qd[r*66 + lc + 3] = make_float2(qw, qw);
    }
#pragma unroll
    for (int rr = 0; rr < 8; rr++) {      // P rows 0..127 transposed [d][k]
        int r = lr + rr*16;
        float4 pv = *(const float4*)&Pg[(size_t)(k0 + r)*DK_ + lc];
        Pt[(lc + 0)*132 + r] = pv.x;
        Pt[(lc + 1)*132 + r] = pv.y;
        Pt[(lc + 2)*132 + r] = pv.z;
        Pt[(lc + 3)*132 + r] = pv.w;
    }
    __syncthreads();

    u64 acc[4][4];
#pragma unroll
    for (int i = 0; i < 4; i++)
#pragma unroll
        for (int j = 0; j < 4; j++) acc[i][j] = 0ull;

#pragma unroll 2
    for (int d = 0; d < 64; d += 2) {
        ulonglong2 av2[4];
#pragma unroll
        for (int i = 0; i < 4; i++)
            av2[i] = *(const ulonglong2*)&Qd[(ty4 + i)*66 + d];
        ulonglong2 b00 = *(const ulonglong2*)&Pt[d*132 + tx*4];
        ulonglong2 b01 = *(const ulonglong2*)&Pt[d*132 + 64 + tx*4];
        ulonglong2 b10 = *(const ulonglong2*)&Pt[(d+1)*132 + tx*4];
        ulonglong2 b11 = *(const ulonglong2*)&Pt[(d+1)*132 + 64 + tx*4];
#pragma unroll
        for (int i = 0; i < 4; i++) {
            fma2(acc[i][0], av2[i].x, b00.x);
            fma2(acc[i][1], av2[i].x, b00.y);
            fma2(acc[i][2], av2[i].x, b01.x);
            fma2(acc[i][3], av2[i].x, b01.y);
            fma2(acc[i][0], av2[i].y, b10.x);
            fma2(acc[i][1], av2[i].y, b10.y);
            fma2(acc[i][2], av2[i].y, b11.x);
            fma2(acc[i][3], av2[i].y, b11.y);
        }
    }

    float* Ao = Ag0 + (size_t)bh * S_ * S_;
#pragma unroll
    for (int i = 0; i < 4; i++) {
        const int gi  = i0 + ty4 + i;
        const int thr = S_ - 1 - gi;           // k >= thr -> row gi
        float* row_hi = Ao + (size_t)gi*S_ - thr;            // + k
        float* row_lo = Ao + (size_t)(gi - 1)*S_ + gi + 1;   // + k (gi>=1)
#pragma unroll
        for (int g = 0; g < 2; g++) {
            float2 v0 = unp(acc[i][g*2]);
            float2 v1 = unp(acc[i][g*2 + 1]);
            float vq[4] = {v0.x, v0.y, v1.x, v1.y};
            const int kq = k0 + g*64 + tx*4;
#pragma unroll
            for (int q = 0; q < 4; q++) {
                const int k = kq + q;
                if (k >= thr)       row_hi[k] = vq[q];
                else if (gi >= 1)   row_lo[k] = vq[q];
            }
        }
    }
}

// ---------------------------------------------------------------------------
// Fused flash attention. BM=64, BN=128, f32x2.  A is PRE-SHIFTED ->
// contiguous LDG.64 pos-score loads (zero-select on the j==i+1 diagonal).
// V tile loaded via cp.async (no register round-trip / STS chain).
// smem: Qd 33280 + U 33280 + Vs 32768 = 99328 B (2 blocks/SM).
// ---------------------------------------------------------------------------
__global__ __launch_bounds__(256, 2) void flash_kernel(
    const float* __restrict__ Qg0, const float* __restrict__ Kg0,
    const float* __restrict__ Vg0, const float* __restrict__ Ag0,
    const float* __restrict__ u_bias, float* __restrict__ ctx)
{
    extern __shared__ float sm[];
    float2* Qd = (float2*)sm;          // [64*65] float2 dup((Q+u)*SCALE)
    float*  U  = sm + 2*64*65;         // [64*130]: Kt [d][col] / p [row][col]
    float*  Vs = U + 64*130;           // [128*64]

    const int tid = threadIdx.x;
    const int ty4 = (tid >> 4) * 4;
    const int tx  = tid & 15;
    const int i0 = blockIdx.x * 64;
    const int h = blockIdx.y, b = blockIdx.z;
    const int bh = b*H_ + h;
    const float* Qg = Qg0 + (size_t)bh * S_ * DK_;
    const float* Kg = Kg0 + (size_t)bh * S_ * DK_;
    const float* Vg = Vg0 + (size_t)bh * S_ * DK_;
    const float* Ag = Ag0 + (size_t)bh * S_ * S_;
    const u32 vs_base = s2u(Vs);

    const int lr = tid >> 4;
    const int lc = (tid & 15) * 4;
#pragma unroll
    for (int rr = 0; rr < 4; rr++) {
        int r = lr + rr*16;
        float4 qv = *(const float4*)&Qg[(size_t)(i0 + r)*DK_ + lc];
        const float4 ub = *(const float4*)&u_bias[h*DK_ + lc];
        float qx = (qv.x + ub.x) * SCALE_;
        float qy = (qv.y + ub.y) * SCALE_;
        float qz = (qv.z + ub.z) * SCALE_;
        float qw = (qv.w + ub.w) * SCALE_;
        Qd[r*65 + lc + 0] = make_float2(qx, qx);
        Qd[r*65 + lc + 1] = make_float2(qy, qy);
        Qd[r*65 + lc + 2] = make_float2(qz, qz);
        Qd[r*65 + lc + 3] = make_float2(qw, qw);
    }

    float m[4], l[4];
    u64 O[4][2];
#pragma unroll
    for (int i = 0; i < 4; i++) {
        m[i] = -3.0e38f; l[i] = 0.f;
        O[i][0] = 0ull; O[i][1] = 0ull;
    }

    for (int jt = 0; jt < S_/128; jt++) {
        const int j0 = jt * 128;
        __syncthreads();   // prev iter's U(p)/Vs reads done (covers Qd @jt=0)

        // V tile via cp.async (row-major, used as-is)
#pragma unroll
        for (int rr = 0; rr < 4; rr++) {
            int r = lr + rr*16 + (rr & 1)*64;   // rows lr+0,lr+80,lr+32,lr+112
            // simpler: cover rows 0..127 as lr + rr*32? need 4 rows of 128:
        }
        // (use straightforward mapping: rows lr, lr+16, ..., lr+112 in 8 steps
        //  of 16 would need 8 cp.asyncs of 16B covering 64 floats/row in quads)
#pragma unroll
        for (int rr = 0; rr < 8; rr++) {
            int r = lr + rr*16;
            cpasync16(vs_base + (u32)((r*64 + lc)*4),
                      &Vg[(size_t)(j0 + r)*DK_ + lc]);
        }
        asm volatile("cp.async.commit_group;" ::: "memory");

        // K tile: LDG + transposed STS into U
#pragma unroll
        for (int rr = 0; rr < 8; rr++) {
            int r = lr + rr*16;
            float4 kv = *(const float4*)&Kg[(size_t)(j0 + r)*DK_ + lc];
            U[(lc + 0)*130 + r] = kv.x;
            U[(lc + 1)*130 + r] = kv.y;
            U[(lc + 2)*130 + r] = kv.z;
            U[(lc + 3)*130 + r] = kv.w;
        }

        // ---- prefetch pre-shifted pos scores: contiguous LDG.64 ----
        float ap[4][8];
#pragma unroll
        for (int i = 0; i < 4; i++) {
            const int gi = i0 + ty4 + i;
            const float* Arow = Ag + (size_t)gi * S_;
#pragma unroll
            for (int j = 0; j < 4; j++) {
                const int c0 = j0 + j*32 + tx*2;
                float2 av = __ldg((const float2*)&Arow[c0]);
                ap[i][j*2]     = (c0     == gi + 1) ? 0.f : av.x;
                ap[i][j*2 + 1] = (c0 + 1 == gi + 1) ? 0.f : av.y;
            }
        }
        asm volatile("cp.async.wait_group 0;" ::: "memory");
        __syncthreads();

        // ---- content scores: ((Q+u)*SCALE) . K ----
        u64 acc[4][4];
#pragma unroll
        for (int i = 0; i < 4; i++)
#pragma unroll
            for (int j = 0; j < 4; j++) acc[i][j] = 0ull;
#pragma unroll 4
        for (int d = 0; d < 64; d++) {
            u64 av[4], bv[4];
#pragma unroll
            for (int i = 0; i < 4; i++)
                av[i] = *(const u64*)&Qd[(ty4 + i)*65 + d];
#pragma unroll
            for (int j = 0; j < 4; j++)
                bv[j] = *(const u64*)&U[d*130 + j*32 + tx*2];
#pragma unroll
            for (int i = 0; i < 4; i++)
#pragma unroll
                for (int j = 0; j < 4; j++)
                    fma2(acc[i][j], av[i], bv[j]);
        }

        // ---- combine prescaled pos score, online softmax ----
        float ps[4][8];
#pragma unroll
        for (int i = 0; i < 4; i++) {
            float rmax = -3.0e38f;
#pragma unroll
            for (int j = 0; j < 4; j++) {
                float2 sc = unp(acc[i][j]);
                float s0 = sc.x + ap[i][j*2];
                float s1 = sc.y + ap[i][j*2 + 1];
                ps[i][j*2]     = s0;
                ps[i][j*2 + 1] = s1;
                rmax = fmaxf(rmax, fmaxf(s0, s1));
            }
#pragma unroll
            for (int o = 8; o >= 1; o >>= 1)
                rmax = fmaxf(rmax, __shfl_xor_sync(0xffffffffu, rmax, o));
            const float mnew  = fmaxf(m[i], rmax);
            const float alpha = __expf(m[i] - mnew);
            float rsum = 0.f;
#pragma unroll
            for (int jj = 0; jj < 8; jj++) {
                float e = __expf(ps[i][jj] - mnew);
                ps[i][jj] = e;
                rsum += e;
            }
#pragma unroll
            for (int o = 8; o >= 1; o >>= 1)
                rsum += __shfl_xor_sync(0xffffffffu, rsum, o);
            l[i] = l[i]*alpha + rsum;
            m[i] = mnew;
            const u64 al = dup2(alpha);
            O[i][0] = mul2(O[i][0], al);
            O[i][1] = mul2(O[i][1], al);
        }

        __syncthreads();   // ALL warps done reading Kt before U <- p
#pragma unroll
        for (int i = 0; i < 4; i++)
#pragma unroll
            for (int j = 0; j < 4; j++)
                *(float2*)&U[(ty4 + i)*130 + j*32 + tx*2] =
                    make_float2(ps[i][j*2], ps[i][j*2 + 1]);
        __syncwarp();      // p rows written & read by the same half-warp

        // ---- O += p @ V ----
#pragma unroll 2
        for (int j = 0; j < 128; j++) {
            u64 a2[4];
#pragma unroll
            for (int i = 0; i < 4; i++)
                a2[i] = dup2(U[(ty4 + i)*130 + j]);
            u64 bv0 = *(const u64*)&Vs[j*64 + tx*2];
            u64 bv1 = *(const u64*)&Vs[j*64 + 32 + tx*2];
#pragma unroll
            for (int i = 0; i < 4; i++) {
                fma2(O[i][0], a2[i], bv0);
                fma2(O[i][1], a2[i], bv1);
            }
        }
    }

    // epilogue: normalize, write context as [B,S,H*DK]
#pragma unroll
    for (int i = 0; i < 4; i++) {
        const int gi = i0 + ty4 + i;
        const float inv = 1.0f / l[i];
        float2 o0 = unp(O[i][0]); o0.x *= inv; o0.y *= inv;
        float2 o1 = unp(O[i][1]); o1.x *= inv; o1.y *= inv;
        float* dst = &ctx[((size_t)b*S_ + gi)*DM_ + h*DK_];
        *(float2*)&dst[tx*2]      = o0;
        *(float2*)&dst[32 + tx*2] = o1;
    }
}

// ---------------------------------------------------------------------------
extern "C" void kernel_launch(void* const* d_in, const int* in_sizes, int n_in,
                              void* d_out, int out_size)
{
    (void)in_sizes; (void)n_in; (void)out_size;
    const float* inputs  = (const float*)d_in[0];
    const float* pos_enc = (const float*)d_in[1];
    const float* W_q     = (const float*)d_in[2];
    const float* W_k     = (const float*)d_in[3];
    const float* W_v     = (const float*)d_in[4];
    const float* W_o     = (const float*)d_in[5];
    const float* W_pos   = (const float*)d_in[6];
    const float* u_b     = (const float*)d_in[7];
    const float* v_b     = (const float*)d_in[8];
    float* out = (float*)d_out;

    float *qp, *kp, *vp, *pp, *ap, *cp;
    cudaGetSymbolAddress((void**)&qp, g_Q);
    cudaGetSymbolAddress((void**)&kp, g_K);
    cudaGetSymbolAddress((void**)&vp, g_V);
    cudaGetSymbolAddress((void**)&pp, g_P);
    cudaGetSymbolAddress((void**)&ap, g_A);
    cudaGetSymbolAddress((void**)&cp, g_ctx);

    const int POSA_SMEM  = (2*64*66 + 64*132) * (int)sizeof(float);           // 67584
    const int FLASH_SMEM = (2*64*65 + 64*130 + 128*64) * (int)sizeof(float);  // 99328
    cudaFuncSetAttribute(posA_kernel,
                         cudaFuncAttributeMaxDynamicSharedMemorySize, POSA_SMEM);
    cudaFuncSetAttribute(flash_kernel,
                         cudaFuncAttributeMaxDynamicSharedMemorySize, FLASH_SMEM);
    cudaFuncSetAttribute(posA_kernel,
                         cudaFuncAttributePreferredSharedMemoryCarveout, 100);
    cudaFuncSetAttribute(flash_kernel,
                         cudaFuncAttributePreferredSharedMemoryCarveout, 100);

    const dim3 thr(256);
    // fused Q/K/V projections (head-split layout)
    qkv_kernel<<<dim3(128, 4, 3), thr>>>(inputs, W_q, W_k, W_v, qp, kp, vp);
    // pos projection
    gemm512_kernel<1><<<dim3(32, 4), thr>>>(pos_enc, W_pos, pp);
    // pre-shifted pos matrix
    posA_kernel<<<dim3(16, 32, 32), thr, POSA_SMEM>>>(qp, pp, v_b, ap);
    // fused attention -> g_ctx
    flash_kernel<<<dim3(32, 8, 4), thr, FLASH_SMEM>>>(qp, kp, vp, ap, u_b, cp);
    // output projection: ctx @ W_o -> out
    gemm512_kernel<0><<<dim3(128, 4), thr>>>(cp, W_o, out);
}